// round 13
// baseline (speedup 1.0000x reference)
#include <cuda_runtime.h>

#define AA   64
#define TT   512
#define DD   256
#define HH   4
#define HDIM 64
#define AT   (AA*TT)

typedef unsigned long long ull;

// Scratch (allocation-free)
__device__ float g_q[AT*DD];
__device__ float g_k[AT*DD];
__device__ float g_v[AT*DD];
__device__ float g_ctx[AT*DD];

// ---------------------------------------------------------------------------
// f32x2 packed-math helpers (base-sm_103 FFMA2 path — ptxas never auto-emits)
// ---------------------------------------------------------------------------
__device__ __forceinline__ ull dup2(float x) {
    ull r;
    asm("mov.b64 %0, {%1, %1};" : "=l"(r) : "r"(__float_as_uint(x)));
    return r;
}
__device__ __forceinline__ void fma2(ull &d, ull a, ull b) {
    asm("fma.rn.f32x2 %0, %1, %2, %0;" : "+l"(d) : "l"(a), "l"(b));
}
__device__ __forceinline__ ull mul2(ull a, ull b) {
    ull r;
    asm("mul.rn.f32x2 %0, %1, %2;" : "=l"(r) : "l"(a), "l"(b));
    return r;
}
__device__ __forceinline__ float2 unpack2(ull v) {
    float2 f;
    asm("mov.b64 {%0, %1}, %2;" : "=f"(f.x), "=f"(f.y) : "l"(v));
    return f;
}

// ---------------------------------------------------------------------------
// GEMM (exact R8): BM=BN=128, BK=16, double-buffered, FFMA2.
// ---------------------------------------------------------------------------
__device__ __forceinline__ void gemm_tile(
    const float (* __restrict__ Ak)[132], const float (* __restrict__ Bk)[132],
    int tx, int ty, ull acc[8][4])
{
    #pragma unroll
    for (int k = 0; k < 16; k++) {
        const float4     a0 = *(const float4*)&Ak[k][ty << 2];
        const float4     a1 = *(const float4*)&Ak[k][64 + (ty << 2)];
        const ulonglong2 b0 = *(const ulonglong2*)&Bk[k][tx << 2];
        const ulonglong2 b1 = *(const ulonglong2*)&Bk[k][64 + (tx << 2)];
        ull am[8] = { dup2(a0.x), dup2(a0.y), dup2(a0.z), dup2(a0.w),
                      dup2(a1.x), dup2(a1.y), dup2(a1.z), dup2(a1.w) };
        #pragma unroll
        for (int mi = 0; mi < 8; mi++) {
            fma2(acc[mi][0], am[mi], b0.x);
            fma2(acc[mi][1], am[mi], b0.y);
            fma2(acc[mi][2], am[mi], b1.x);
            fma2(acc[mi][3], am[mi], b1.y);
        }
    }
}

__device__ __forceinline__ void gemm_body(
    const float* __restrict__ X, const float* __restrict__ W,
    const float* __restrict__ bias, float* __restrict__ Y,
    int m0, int n0)
{
    __shared__ float As[2][16][132];
    __shared__ float Bs[2][16][132];

    const int tid = threadIdx.x;
    const int tx  = tid & 15;
    const int ty  = tid >> 4;
    const int lr  = tid >> 2;
    const int lc  = (tid & 3) << 2;

    ull acc[8][4];
    #pragma unroll
    for (int i = 0; i < 8; i++)
        #pragma unroll
        for (int j = 0; j < 4; j++) acc[i][j] = 0ull;

    const float* xp0 = &X[(size_t)(m0 + lr)      * DD + lc];
    const float* xp1 = &X[(size_t)(m0 + 64 + lr) * DD + lc];
    const float* wp0 = &W[(size_t)(n0 + lr)      * DD + lc];
    const float* wp1 = &W[(size_t)(n0 + 64 + lr) * DD + lc];

    {
        float4 x0 = *(const float4*)(xp0);
        float4 x1 = *(const float4*)(xp1);
        float4 w0 = *(const float4*)(wp0);
        float4 w1 = *(const float4*)(wp1);
        As[0][lc+0][lr] = x0.x; As[0][lc+1][lr] = x0.y; As[0][lc+2][lr] = x0.z; As[0][lc+3][lr] = x0.w;
        As[0][lc+0][64+lr] = x1.x; As[0][lc+1][64+lr] = x1.y; As[0][lc+2][64+lr] = x1.z; As[0][lc+3][64+lr] = x1.w;
        Bs[0][lc+0][lr] = w0.x; Bs[0][lc+1][lr] = w0.y; Bs[0][lc+2][lr] = w0.z; Bs[0][lc+3][lr] = w0.w;
        Bs[0][lc+0][64+lr] = w1.x; Bs[0][lc+1][64+lr] = w1.y; Bs[0][lc+2][64+lr] = w1.z; Bs[0][lc+3][64+lr] = w1.w;
    }
    __syncthreads();

    int p = 0;
    for (int k0 = 16; k0 < 256; k0 += 16) {
        float4 x0 = *(const float4*)(xp0 + k0);
        float4 x1 = *(const float4*)(xp1 + k0);
        float4 w0 = *(const float4*)(wp0 + k0);
        float4 w1 = *(const float4*)(wp1 + k0);

        gemm_tile(As[p], Bs[p], tx, ty, acc);

        const int q = p ^ 1;
        As[q][lc+0][lr] = x0.x; As[q][lc+1][lr] = x0.y; As[q][lc+2][lr] = x0.z; As[q][lc+3][lr] = x0.w;
        As[q][lc+0][64+lr] = x1.x; As[q][lc+1][64+lr] = x1.y; As[q][lc+2][64+lr] = x1.z; As[q][lc+3][64+lr] = x1.w;
        Bs[q][lc+0][lr] = w0.x; Bs[q][lc+1][lr] = w0.y; Bs[q][lc+2][lr] = w0.z; Bs[q][lc+3][lr] = w0.w;
        Bs[q][lc+0][64+lr] = w1.x; Bs[q][lc+1][64+lr] = w1.y; Bs[q][lc+2][64+lr] = w1.z; Bs[q][lc+3][64+lr] = w1.w;
        __syncthreads();
        p = q;
    }
    gemm_tile(As[p], Bs[p], tx, ty, acc);

    float4 bv0 = *(const float4*)&bias[n0 + (tx << 2)];
    float4 bv1 = *(const float4*)&bias[n0 + 64 + (tx << 2)];
    #pragma unroll
    for (int mi = 0; mi < 8; mi++) {
        const int m = m0 + ((mi < 4) ? ((ty << 2) + mi) : (64 + (ty << 2) + mi - 4));
        float2 p0 = unpack2(acc[mi][0]);
        float2 p1 = unpack2(acc[mi][1]);
        float4 r0 = { p0.x + bv0.x, p0.y + bv0.y, p1.x + bv0.z, p1.y + bv0.w };
        *(float4*)&Y[(size_t)m * DD + n0 + (tx << 2)] = r0;
        float2 p2 = unpack2(acc[mi][2]);
        float2 p3 = unpack2(acc[mi][3]);
        float4 r1 = { p2.x + bv1.x, p2.y + bv1.y, p3.x + bv1.z, p3.y + bv1.w };
        *(float4*)&Y[(size_t)m * DD + n0 + 64 + (tx << 2)] = r1;
    }
}

__global__ __launch_bounds__(256, 2) void gemm_qkv(
    const float* __restrict__ X,
    const float* __restrict__ Wq, const float* __restrict__ Wk, const float* __restrict__ Wv,
    const float* __restrict__ bq, const float* __restrict__ bk, const float* __restrict__ bv,
    float* __restrict__ Yq, float* __restrict__ Yk, float* __restrict__ Yv)
{
    const int z = blockIdx.z;
    const float* W = (z == 0) ? Wq : (z == 1) ? Wk : Wv;
    const float* b = (z == 0) ? bq : (z == 1) ? bk : bv;
    float*       Y = (z == 0) ? Yq : (z == 1) ? Yk : Yv;
    gemm_body(X, W, b, Y, blockIdx.x * 128, blockIdx.y * 128);
}

__global__ __launch_bounds__(256, 2) void gemm_single(
    const float* __restrict__ X, const float* __restrict__ W,
    const float* __restrict__ bias, float* __restrict__ Y)
{
    gemm_body(X, W, bias, Y, blockIdx.x * 128, blockIdx.y * 128);
}

// ---------------------------------------------------------------------------
// Banded sparse attention.  Staging/scores identical to the 587.8us kernel.
// CHANGES: (1) AV reads probs from smem Ps2 (dup-packed, broadcast LDS) —
// no shfl/mov in the AV inner loop; (2) per-chunk sum butterfly removed —
// per-lane partial normalizer, single butterfly at the end.
// Launched in 4 a-group slices (diagnostic: makes ncu capture attn likely).
// ---------------------------------------------------------------------------
__global__ __launch_bounds__(256, 3) void attn_banded(
    const float* __restrict__ pos,
    const int* __restrict__ p_md, const int* __restrict__ p_tw, int a0)
{
    __shared__ float Qs[32][68];
    __shared__ float Ks[32][68];
    __shared__ float Vs[32][68];
    __shared__ ull   Ps2[32][32];   // probs [q][key], dup-packed

    const int a    = a0 + blockIdx.z;
    const int h    = blockIdx.y;
    const int q0   = blockIdx.x * 32;
    const int tid  = threadIdx.x;
    const int w    = tid >> 5;
    const int lane = tid & 31;
    const int w4   = w << 2;

    const int   tw  = *p_tw;
    const float mdf = (float)(*p_md);
    const float md2 = mdf * mdf;

    {
        const float* qbase = g_q + (size_t)(a*TT + q0) * DD + h*HDIM;
        #pragma unroll
        for (int i = tid; i < 32*16; i += 256) {
            const int r  = i >> 4;
            const int c4 = (i & 15) << 2;
            float4 v = *(const float4*)&qbase[(size_t)r * DD + c4];
            v.x *= 0.125f; v.y *= 0.125f; v.z *= 0.125f; v.w *= 0.125f;
            *(float4*)&Qs[r][c4] = v;
        }
    }

    float pqx[4], pqy[4];
    #pragma unroll
    for (int i = 0; i < 4; i++) {
        const int qg = q0 + w4 + i;
        pqx[i] = pos[(size_t)(a*TT + qg)*2 + 0];
        pqy[i] = pos[(size_t)(a*TT + qg)*2 + 1];
    }
    float mrow[4]  = {-1e30f, -1e30f, -1e30f, -1e30f};
    float lpart[4] = {0.f, 0.f, 0.f, 0.f};     // per-lane partial normalizer
    ull   o2[4]    = {0ull, 0ull, 0ull, 0ull};

    int jlo = q0 - tw;       if (jlo < 0)      jlo = 0;
    int jhi = q0 + 31 + tw;  if (jhi > TT - 1) jhi = TT - 1;

    for (int c0 = jlo; c0 <= jhi; c0 += 32) {
        const int cn = min(32, jhi - c0 + 1);

        __syncthreads();
        {
            const float* kbase = g_k + (size_t)(a*TT + c0) * DD + h*HDIM;
            const float* vbase = g_v + (size_t)(a*TT + c0) * DD + h*HDIM;
            #pragma unroll
            for (int i = tid; i < 32*16; i += 256) {
                const int r  = i >> 4;
                const int c4 = (i & 15) << 2;
                if (r < cn) {
                    *(float4*)&Ks[r][c4] = *(const float4*)&kbase[(size_t)r * DD + c4];
                    *(float4*)&Vs[r][c4] = *(const float4*)&vbase[(size_t)r * DD + c4];
                } else {
                    const float4 z = {0.f, 0.f, 0.f, 0.f};
                    *(float4*)&Vs[r][c4] = z;
                }
            }
        }
        __syncthreads();

        // ---- scores (lane = key in chunk) ----
        const int  jg   = c0 + lane;
        const bool lval = (lane < cn);
        float pkx = 0.f, pky = 0.f;
        if (lval) {
            pkx = pos[(size_t)(a*TT + jg)*2 + 0];
            pky = pos[(size_t)(a*TT + jg)*2 + 1];
        }

        ull s2[4] = {0ull, 0ull, 0ull, 0ull};
        #pragma unroll
        for (int d4 = 0; d4 < 16; d4++) {
            ulonglong2 kk = *(const ulonglong2*)&Ks[lane][d4 << 2];
            #pragma unroll
            for (int i = 0; i < 4; i++) {
                ulonglong2 qq = *(const ulonglong2*)&Qs[w4 + i][d4 << 2];
                fma2(s2[i], qq.x, kk.x);
                fma2(s2[i], qq.y, kk.y);
            }
        }

        #pragma unroll
        for (int i = 0; i < 4; i++) {
            float2 sv = unpack2(s2[i]);
            float  s  = sv.x + sv.y;

            const int qg = q0 + w4 + i;
            int dt = qg - jg; dt = dt < 0 ? -dt : dt;
            const float dx = pqx[i] - pkx;
            const float dy = pqy[i] - pky;
            const bool ok = lval && (dt <= tw) && (dx*dx + dy*dy <= md2);
            if (!ok) s = -1e30f;

            float cm = s;
            #pragma unroll
            for (int off = 16; off; off >>= 1)
                cm = fmaxf(cm, __shfl_xor_sync(0xffffffffu, cm, off));
            const float mi = fmaxf(mrow[i], cm);

            const float p  = ok ? __expf(s - mi) : 0.f;
            const float sf = __expf(mrow[i] - mi);
            lpart[i] = lpart[i] * sf + p;
            mrow[i]  = mi;
            Ps2[w4 + i][lane] = dup2(p);
            o2[i] = mul2(o2[i], dup2(sf));
        }
        __syncwarp();   // Ps2 rows for this warp's queries written by this warp

        // ---- AV (lane = dim pair); p via broadcast LDS, no shfl ----
        #pragma unroll
        for (int j2 = 0; j2 < 16; j2++) {
            const ull vva = *(const ull*)&Vs[2*j2 + 0][lane << 1];
            const ull vvb = *(const ull*)&Vs[2*j2 + 1][lane << 1];
            #pragma unroll
            for (int i = 0; i < 4; i++) {
                const ulonglong2 pp = *(const ulonglong2*)&Ps2[w4 + i][j2 << 1]; // broadcast
                fma2(o2[i], pp.x, vva);
                fma2(o2[i], pp.y, vvb);
            }
        }
    }

    // final normalizer reduce + write context
    #pragma unroll
    for (int i = 0; i < 4; i++) {
        float cs = lpart[i];
        #pragma unroll
        for (int off = 16; off; off >>= 1)
            cs += __shfl_xor_sync(0xffffffffu, cs, off);
        const int   qg  = q0 + w4 + i;
        const float inv = 1.f / cs;
        float2 ov = unpack2(o2[i]);
        float2 r;
        r.x = ov.x * inv;
        r.y = ov.y * inv;
        *(float2*)&g_ctx[(size_t)(a*TT + qg) * DD + h*HDIM + (lane << 1)] = r;
    }
}

// ---------------------------------------------------------------------------
// Launch
// ---------------------------------------------------------------------------
extern "C" void kernel_launch(void* const* d_in, const int* in_sizes, int n_in,
                              void* d_out, int out_size)
{
    const float* feat = (const float*)d_in[0];
    const float* posn = (const float*)d_in[1];
    const float* Wq   = (const float*)d_in[2];
    const float* bq   = (const float*)d_in[3];
    const float* Wk   = (const float*)d_in[4];
    const float* bk   = (const float*)d_in[5];
    const float* Wv   = (const float*)d_in[6];
    const float* bv   = (const float*)d_in[7];
    const float* Wo   = (const float*)d_in[8];
    const float* bo   = (const float*)d_in[9];
    const int*   pmd  = (const int*)d_in[10];
    const int*   ptw  = (const int*)d_in[11];

    void *pq, *pk, *pv, *pctx;
    cudaGetSymbolAddress(&pq,   g_q);
    cudaGetSymbolAddress(&pk,   g_k);
    cudaGetSymbolAddress(&pv,   g_v);
    cudaGetSymbolAddress(&pctx, g_ctx);

    gemm_qkv<<<dim3(AT/128, DD/128, 3), 256>>>(
        feat, Wq, Wk, Wv, bq, bk, bv, (float*)pq, (float*)pk, (float*)pv);

    // 4 a-group slices (same total work; improves ncu capture odds on attn)
    for (int a0 = 0; a0 < AA; a0 += 16)
        attn_banded<<<dim3(TT/32, HH, 16), 256>>>(posn, pmd, ptw, a0);

    gemm_single<<<dim3(AT/128, DD/128, 1), 256>>>(
        (const float*)pctx, Wo, bo, (float*)d_out);
}

// round 14
// speedup vs baseline: 1.0817x; 1.0817x over previous
#include <cuda_runtime.h>

#define AA   64
#define TT   512
#define DD   256
#define HH   4
#define HDIM 64
#define AT   (AA*TT)

typedef unsigned long long ull;

// Scratch (allocation-free)
__device__ float g_q[AT*DD];
__device__ float g_k[AT*DD];
__device__ float g_v[AT*DD];
__device__ float g_ctx[AT*DD];

// ---------------------------------------------------------------------------
// f32x2 packed-math helpers (base-sm_103 FFMA2 path — ptxas never auto-emits)
// ---------------------------------------------------------------------------
__device__ __forceinline__ ull dup2(float x) {
    ull r;
    asm("mov.b64 %0, {%1, %1};" : "=l"(r) : "r"(__float_as_uint(x)));
    return r;
}
__device__ __forceinline__ void fma2(ull &d, ull a, ull b) {
    asm("fma.rn.f32x2 %0, %1, %2, %0;" : "+l"(d) : "l"(a), "l"(b));
}
__device__ __forceinline__ ull mul2(ull a, ull b) {
    ull r;
    asm("mul.rn.f32x2 %0, %1, %2;" : "=l"(r) : "l"(a), "l"(b));
    return r;
}
__device__ __forceinline__ float2 unpack2(ull v) {
    float2 f;
    asm("mov.b64 {%0, %1}, %2;" : "=f"(f.x), "=f"(f.y) : "l"(v));
    return f;
}

// ---------------------------------------------------------------------------
// GEMM (exact R8): BM=BN=128, BK=16, double-buffered, FFMA2.
// ---------------------------------------------------------------------------
__device__ __forceinline__ void gemm_tile(
    const float (* __restrict__ Ak)[132], const float (* __restrict__ Bk)[132],
    int tx, int ty, ull acc[8][4])
{
    #pragma unroll
    for (int k = 0; k < 16; k++) {
        const float4     a0 = *(const float4*)&Ak[k][ty << 2];
        const float4     a1 = *(const float4*)&Ak[k][64 + (ty << 2)];
        const ulonglong2 b0 = *(const ulonglong2*)&Bk[k][tx << 2];
        const ulonglong2 b1 = *(const ulonglong2*)&Bk[k][64 + (tx << 2)];
        ull am[8] = { dup2(a0.x), dup2(a0.y), dup2(a0.z), dup2(a0.w),
                      dup2(a1.x), dup2(a1.y), dup2(a1.z), dup2(a1.w) };
        #pragma unroll
        for (int mi = 0; mi < 8; mi++) {
            fma2(acc[mi][0], am[mi], b0.x);
            fma2(acc[mi][1], am[mi], b0.y);
            fma2(acc[mi][2], am[mi], b1.x);
            fma2(acc[mi][3], am[mi], b1.y);
        }
    }
}

__device__ __forceinline__ void gemm_body(
    const float* __restrict__ X, const float* __restrict__ W,
    const float* __restrict__ bias, float* __restrict__ Y,
    int m0, int n0)
{
    __shared__ float As[2][16][132];
    __shared__ float Bs[2][16][132];

    const int tid = threadIdx.x;
    const int tx  = tid & 15;
    const int ty  = tid >> 4;
    const int lr  = tid >> 2;
    const int lc  = (tid & 3) << 2;

    ull acc[8][4];
    #pragma unroll
    for (int i = 0; i < 8; i++)
        #pragma unroll
        for (int j = 0; j < 4; j++) acc[i][j] = 0ull;

    const float* xp0 = &X[(size_t)(m0 + lr)      * DD + lc];
    const float* xp1 = &X[(size_t)(m0 + 64 + lr) * DD + lc];
    const float* wp0 = &W[(size_t)(n0 + lr)      * DD + lc];
    const float* wp1 = &W[(size_t)(n0 + 64 + lr) * DD + lc];

    {
        float4 x0 = *(const float4*)(xp0);
        float4 x1 = *(const float4*)(xp1);
        float4 w0 = *(const float4*)(wp0);
        float4 w1 = *(const float4*)(wp1);
        As[0][lc+0][lr] = x0.x; As[0][lc+1][lr] = x0.y; As[0][lc+2][lr] = x0.z; As[0][lc+3][lr] = x0.w;
        As[0][lc+0][64+lr] = x1.x; As[0][lc+1][64+lr] = x1.y; As[0][lc+2][64+lr] = x1.z; As[0][lc+3][64+lr] = x1.w;
        Bs[0][lc+0][lr] = w0.x; Bs[0][lc+1][lr] = w0.y; Bs[0][lc+2][lr] = w0.z; Bs[0][lc+3][lr] = w0.w;
        Bs[0][lc+0][64+lr] = w1.x; Bs[0][lc+1][64+lr] = w1.y; Bs[0][lc+2][64+lr] = w1.z; Bs[0][lc+3][64+lr] = w1.w;
    }
    __syncthreads();

    int p = 0;
    for (int k0 = 16; k0 < 256; k0 += 16) {
        float4 x0 = *(const float4*)(xp0 + k0);
        float4 x1 = *(const float4*)(xp1 + k0);
        float4 w0 = *(const float4*)(wp0 + k0);
        float4 w1 = *(const float4*)(wp1 + k0);

        gemm_tile(As[p], Bs[p], tx, ty, acc);

        const int q = p ^ 1;
        As[q][lc+0][lr] = x0.x; As[q][lc+1][lr] = x0.y; As[q][lc+2][lr] = x0.z; As[q][lc+3][lr] = x0.w;
        As[q][lc+0][64+lr] = x1.x; As[q][lc+1][64+lr] = x1.y; As[q][lc+2][64+lr] = x1.z; As[q][lc+3][64+lr] = x1.w;
        Bs[q][lc+0][lr] = w0.x; Bs[q][lc+1][lr] = w0.y; Bs[q][lc+2][lr] = w0.z; Bs[q][lc+3][lr] = w0.w;
        Bs[q][lc+0][64+lr] = w1.x; Bs[q][lc+1][64+lr] = w1.y; Bs[q][lc+2][64+lr] = w1.z; Bs[q][lc+3][64+lr] = w1.w;
        __syncthreads();
        p = q;
    }
    gemm_tile(As[p], Bs[p], tx, ty, acc);

    float4 bv0 = *(const float4*)&bias[n0 + (tx << 2)];
    float4 bv1 = *(const float4*)&bias[n0 + 64 + (tx << 2)];
    #pragma unroll
    for (int mi = 0; mi < 8; mi++) {
        const int m = m0 + ((mi < 4) ? ((ty << 2) + mi) : (64 + (ty << 2) + mi - 4));
        float2 p0 = unpack2(acc[mi][0]);
        float2 p1 = unpack2(acc[mi][1]);
        float4 r0 = { p0.x + bv0.x, p0.y + bv0.y, p1.x + bv0.z, p1.y + bv0.w };
        *(float4*)&Y[(size_t)m * DD + n0 + (tx << 2)] = r0;
        float2 p2 = unpack2(acc[mi][2]);
        float2 p3 = unpack2(acc[mi][3]);
        float4 r1 = { p2.x + bv1.x, p2.y + bv1.y, p3.x + bv1.z, p3.y + bv1.w };
        *(float4*)&Y[(size_t)m * DD + n0 + 64 + (tx << 2)] = r1;
    }
}

__global__ __launch_bounds__(256, 2) void gemm_qkv(
    const float* __restrict__ X,
    const float* __restrict__ Wq, const float* __restrict__ Wk, const float* __restrict__ Wv,
    const float* __restrict__ bq, const float* __restrict__ bk, const float* __restrict__ bv,
    float* __restrict__ Yq, float* __restrict__ Yk, float* __restrict__ Yv)
{
    const int z = blockIdx.z;
    const float* W = (z == 0) ? Wq : (z == 1) ? Wk : Wv;
    const float* b = (z == 0) ? bq : (z == 1) ? bk : bv;
    float*       Y = (z == 0) ? Yq : (z == 1) ? Yk : Yv;
    gemm_body(X, W, b, Y, blockIdx.x * 128, blockIdx.y * 128);
}

__global__ __launch_bounds__(256, 2) void gemm_single(
    const float* __restrict__ X, const float* __restrict__ W,
    const float* __restrict__ bias, float* __restrict__ Y)
{
    gemm_body(X, W, bias, Y, blockIdx.x * 128, blockIdx.y * 128);
}

// ---------------------------------------------------------------------------
// Banded sparse attention — 64-query tile (8 q/warp), crossbar-clean:
//   * Ks/Vs staged plain row-major (conflict-free, as the 587.8us kernel)
//   * K/V/staging crossbar traffic amortized over 2x queries per warp
//   * p broadcast via SHUFFLE network (off the crossbar), as R4
//   * per-lane partial normalizer; single butterfly at the end
// ---------------------------------------------------------------------------
__global__ __launch_bounds__(256, 2) void attn_banded(
    const float* __restrict__ pos,
    const int* __restrict__ p_md, const int* __restrict__ p_tw)
{
    __shared__ float Qs[64][68];
    __shared__ float Ks[32][68];
    __shared__ float Vs[32][68];

    const int a    = blockIdx.z;
    const int h    = blockIdx.y;
    const int q0   = blockIdx.x * 64;
    const int tid  = threadIdx.x;
    const int w    = tid >> 5;
    const int lane = tid & 31;
    const int w8   = w << 3;

    const int   tw  = *p_tw;
    const float mdf = (float)(*p_md);
    const float md2 = mdf * mdf;

    // Stage + pre-scale Q (scale = 1/sqrt(64))
    {
        const float* qbase = g_q + (size_t)(a*TT + q0) * DD + h*HDIM;
        #pragma unroll
        for (int i = tid; i < 64*16; i += 256) {
            const int r  = i >> 4;
            const int c4 = (i & 15) << 2;
            float4 v = *(const float4*)&qbase[(size_t)r * DD + c4];
            v.x *= 0.125f; v.y *= 0.125f; v.z *= 0.125f; v.w *= 0.125f;
            *(float4*)&Qs[r][c4] = v;
        }
    }

    float pqx[8], pqy[8];
    #pragma unroll
    for (int i = 0; i < 8; i++) {
        const int qg = q0 + w8 + i;
        pqx[i] = pos[(size_t)(a*TT + qg)*2 + 0];
        pqy[i] = pos[(size_t)(a*TT + qg)*2 + 1];
    }
    float mrow[8], lpart[8];
    ull   o2[8];
    #pragma unroll
    for (int i = 0; i < 8; i++) { mrow[i] = -1e30f; lpart[i] = 0.f; o2[i] = 0ull; }

    int jlo = q0 - tw;       if (jlo < 0)      jlo = 0;
    int jhi = q0 + 63 + tw;  if (jhi > TT - 1) jhi = TT - 1;

    for (int c0 = jlo; c0 <= jhi; c0 += 32) {
        const int cn = min(32, jhi - c0 + 1);

        __syncthreads();
        {
            const float* kbase = g_k + (size_t)(a*TT + c0) * DD + h*HDIM;
            const float* vbase = g_v + (size_t)(a*TT + c0) * DD + h*HDIM;
            #pragma unroll
            for (int i = tid; i < 32*16; i += 256) {
                const int r  = i >> 4;
                const int c4 = (i & 15) << 2;
                if (r < cn) {
                    *(float4*)&Ks[r][c4] = *(const float4*)&kbase[(size_t)r * DD + c4];
                    *(float4*)&Vs[r][c4] = *(const float4*)&vbase[(size_t)r * DD + c4];
                } else {
                    const float4 z = {0.f, 0.f, 0.f, 0.f};
                    *(float4*)&Vs[r][c4] = z;
                }
            }
        }
        __syncthreads();

        // ---- scores (lane = key in chunk) ----
        const int  jg   = c0 + lane;
        const bool lval = (lane < cn);
        float pkx = 0.f, pky = 0.f;
        if (lval) {
            pkx = pos[(size_t)(a*TT + jg)*2 + 0];
            pky = pos[(size_t)(a*TT + jg)*2 + 1];
        }

        ull s2[8];
        #pragma unroll
        for (int i = 0; i < 8; i++) s2[i] = 0ull;
        #pragma unroll
        for (int d4 = 0; d4 < 16; d4++) {
            ulonglong2 kk = *(const ulonglong2*)&Ks[lane][d4 << 2];
            #pragma unroll
            for (int i = 0; i < 8; i++) {
                ulonglong2 qq = *(const ulonglong2*)&Qs[w8 + i][d4 << 2];  // broadcast
                fma2(s2[i], qq.x, kk.x);
                fma2(s2[i], qq.y, kk.y);
            }
        }

        float p_reg[8], sf[8];
        #pragma unroll
        for (int i = 0; i < 8; i++) {
            float2 sv = unpack2(s2[i]);
            float  s  = sv.x + sv.y;

            const int qg = q0 + w8 + i;
            int dt = qg - jg; dt = dt < 0 ? -dt : dt;
            const float dx = pqx[i] - pkx;
            const float dy = pqy[i] - pky;
            const bool ok = lval && (dt <= tw) && (dx*dx + dy*dy <= md2);
            if (!ok) s = -1e30f;

            float cm = s;
            #pragma unroll
            for (int off = 16; off; off >>= 1)
                cm = fmaxf(cm, __shfl_xor_sync(0xffffffffu, cm, off));
            const float mi = fmaxf(mrow[i], cm);

            const float p = ok ? __expf(s - mi) : 0.f;
            sf[i]    = __expf(mrow[i] - mi);
            lpart[i] = lpart[i] * sf[i] + p;
            mrow[i]  = mi;
            p_reg[i] = p;
        }

        #pragma unroll
        for (int i = 0; i < 8; i++)
            o2[i] = mul2(o2[i], dup2(sf[i]));

        // ---- AV (lane = dim pair); p via shuffle network (off-crossbar) ----
        #pragma unroll
        for (int j = 0; j < 32; j++) {
            ull vv = *(const ull*)&Vs[j][lane << 1];
            #pragma unroll
            for (int i = 0; i < 8; i++) {
                float pj = __shfl_sync(0xffffffffu, p_reg[i], j);
                fma2(o2[i], dup2(pj), vv);
            }
        }
    }

    // final normalizer reduce + write context
    #pragma unroll
    for (int i = 0; i < 8; i++) {
        float cs = lpart[i];
        #pragma unroll
        for (int off = 16; off; off >>= 1)
            cs += __shfl_xor_sync(0xffffffffu, cs, off);
        const int   qg  = q0 + w8 + i;
        const float inv = 1.f / cs;
        float2 ov = unpack2(o2[i]);
        float2 r;
        r.x = ov.x * inv;
        r.y = ov.y * inv;
        *(float2*)&g_ctx[(size_t)(a*TT + qg) * DD + h*HDIM + (lane << 1)] = r;
    }
}

// ---------------------------------------------------------------------------
// Launch
// ---------------------------------------------------------------------------
extern "C" void kernel_launch(void* const* d_in, const int* in_sizes, int n_in,
                              void* d_out, int out_size)
{
    const float* feat = (const float*)d_in[0];
    const float* posn = (const float*)d_in[1];
    const float* Wq   = (const float*)d_in[2];
    const float* bq   = (const float*)d_in[3];
    const float* Wk   = (const float*)d_in[4];
    const float* bk   = (const float*)d_in[5];
    const float* Wv   = (const float*)d_in[6];
    const float* bv   = (const float*)d_in[7];
    const float* Wo   = (const float*)d_in[8];
    const float* bo   = (const float*)d_in[9];
    const int*   pmd  = (const int*)d_in[10];
    const int*   ptw  = (const int*)d_in[11];

    void *pq, *pk, *pv, *pctx;
    cudaGetSymbolAddress(&pq,   g_q);
    cudaGetSymbolAddress(&pk,   g_k);
    cudaGetSymbolAddress(&pv,   g_v);
    cudaGetSymbolAddress(&pctx, g_ctx);

    gemm_qkv<<<dim3(AT/128, DD/128, 3), 256>>>(
        feat, Wq, Wk, Wv, bq, bk, bv, (float*)pq, (float*)pk, (float*)pv);

    attn_banded<<<dim3(TT/64, HH, AA), 256>>>(posn, pmd, ptw);

    gemm_single<<<dim3(AT/128, DD/128, 1), 256>>>(
        (const float*)pctx, Wo, bo, (float*)d_out);
}

// round 16
// speedup vs baseline: 1.2008x; 1.1101x over previous
#include <cuda_runtime.h>

#define AA   64
#define TT   512
#define DD   256
#define HH   4
#define HDIM 64
#define AT   (AA*TT)

typedef unsigned long long ull;

// Scratch (allocation-free)
__device__ float g_q[AT*DD];
__device__ float g_k[AT*DD];
__device__ float g_v[AT*DD];
__device__ float g_ctx[AT*DD];

// ---------------------------------------------------------------------------
// f32x2 packed-math helpers (base-sm_103 FFMA2 path — ptxas never auto-emits)
// ---------------------------------------------------------------------------
__device__ __forceinline__ ull dup2(float x) {
    ull r;
    asm("mov.b64 %0, {%1, %1};" : "=l"(r) : "r"(__float_as_uint(x)));
    return r;
}
__device__ __forceinline__ void fma2(ull &d, ull a, ull b) {
    asm("fma.rn.f32x2 %0, %1, %2, %0;" : "+l"(d) : "l"(a), "l"(b));
}
__device__ __forceinline__ ull mul2(ull a, ull b) {
    ull r;
    asm("mul.rn.f32x2 %0, %1, %2;" : "=l"(r) : "l"(a), "l"(b));
    return r;
}
__device__ __forceinline__ float2 unpack2(ull v) {
    float2 f;
    asm("mov.b64 {%0, %1}, %2;" : "=f"(f.x), "=f"(f.y) : "l"(v));
    return f;
}

// ---------------------------------------------------------------------------
// GEMM (exact R8): BM=BN=128, BK=16, double-buffered, FFMA2.
// ---------------------------------------------------------------------------
__device__ __forceinline__ void gemm_tile(
    const float (* __restrict__ Ak)[132], const float (* __restrict__ Bk)[132],
    int tx, int ty, ull acc[8][4])
{
    #pragma unroll
    for (int k = 0; k < 16; k++) {
        const float4     a0 = *(const float4*)&Ak[k][ty << 2];
        const float4     a1 = *(const float4*)&Ak[k][64 + (ty << 2)];
        const ulonglong2 b0 = *(const ulonglong2*)&Bk[k][tx << 2];
        const ulonglong2 b1 = *(const ulonglong2*)&Bk[k][64 + (tx << 2)];
        ull am[8] = { dup2(a0.x), dup2(a0.y), dup2(a0.z), dup2(a0.w),
                      dup2(a1.x), dup2(a1.y), dup2(a1.z), dup2(a1.w) };
        #pragma unroll
        for (int mi = 0; mi < 8; mi++) {
            fma2(acc[mi][0], am[mi], b0.x);
            fma2(acc[mi][1], am[mi], b0.y);
            fma2(acc[mi][2], am[mi], b1.x);
            fma2(acc[mi][3], am[mi], b1.y);
        }
    }
}

__device__ __forceinline__ void gemm_body(
    const float* __restrict__ X, const float* __restrict__ W,
    const float* __restrict__ bias, float* __restrict__ Y,
    int m0, int n0)
{
    __shared__ float As[2][16][132];
    __shared__ float Bs[2][16][132];

    const int tid = threadIdx.x;
    const int tx  = tid & 15;
    const int ty  = tid >> 4;
    const int lr  = tid >> 2;
    const int lc  = (tid & 3) << 2;

    ull acc[8][4];
    #pragma unroll
    for (int i = 0; i < 8; i++)
        #pragma unroll
        for (int j = 0; j < 4; j++) acc[i][j] = 0ull;

    const float* xp0 = &X[(size_t)(m0 + lr)      * DD + lc];
    const float* xp1 = &X[(size_t)(m0 + 64 + lr) * DD + lc];
    const float* wp0 = &W[(size_t)(n0 + lr)      * DD + lc];
    const float* wp1 = &W[(size_t)(n0 + 64 + lr) * DD + lc];

    {
        float4 x0 = *(const float4*)(xp0);
        float4 x1 = *(const float4*)(xp1);
        float4 w0 = *(const float4*)(wp0);
        float4 w1 = *(const float4*)(wp1);
        As[0][lc+0][lr] = x0.x; As[0][lc+1][lr] = x0.y; As[0][lc+2][lr] = x0.z; As[0][lc+3][lr] = x0.w;
        As[0][lc+0][64+lr] = x1.x; As[0][lc+1][64+lr] = x1.y; As[0][lc+2][64+lr] = x1.z; As[0][lc+3][64+lr] = x1.w;
        Bs[0][lc+0][lr] = w0.x; Bs[0][lc+1][lr] = w0.y; Bs[0][lc+2][lr] = w0.z; Bs[0][lc+3][lr] = w0.w;
        Bs[0][lc+0][64+lr] = w1.x; Bs[0][lc+1][64+lr] = w1.y; Bs[0][lc+2][64+lr] = w1.z; Bs[0][lc+3][64+lr] = w1.w;
    }
    __syncthreads();

    int p = 0;
    for (int k0 = 16; k0 < 256; k0 += 16) {
        float4 x0 = *(const float4*)(xp0 + k0);
        float4 x1 = *(const float4*)(xp1 + k0);
        float4 w0 = *(const float4*)(wp0 + k0);
        float4 w1 = *(const float4*)(wp1 + k0);

        gemm_tile(As[p], Bs[p], tx, ty, acc);

        const int q = p ^ 1;
        As[q][lc+0][lr] = x0.x; As[q][lc+1][lr] = x0.y; As[q][lc+2][lr] = x0.z; As[q][lc+3][lr] = x0.w;
        As[q][lc+0][64+lr] = x1.x; As[q][lc+1][64+lr] = x1.y; As[q][lc+2][64+lr] = x1.z; As[q][lc+3][64+lr] = x1.w;
        Bs[q][lc+0][lr] = w0.x; Bs[q][lc+1][lr] = w0.y; Bs[q][lc+2][lr] = w0.z; Bs[q][lc+3][lr] = w0.w;
        Bs[q][lc+0][64+lr] = w1.x; Bs[q][lc+1][64+lr] = w1.y; Bs[q][lc+2][64+lr] = w1.z; Bs[q][lc+3][64+lr] = w1.w;
        __syncthreads();
        p = q;
    }
    gemm_tile(As[p], Bs[p], tx, ty, acc);

    float4 bv0 = *(const float4*)&bias[n0 + (tx << 2)];
    float4 bv1 = *(const float4*)&bias[n0 + 64 + (tx << 2)];
    #pragma unroll
    for (int mi = 0; mi < 8; mi++) {
        const int m = m0 + ((mi < 4) ? ((ty << 2) + mi) : (64 + (ty << 2) + mi - 4));
        float2 p0 = unpack2(acc[mi][0]);
        float2 p1 = unpack2(acc[mi][1]);
        float4 r0 = { p0.x + bv0.x, p0.y + bv0.y, p1.x + bv0.z, p1.y + bv0.w };
        *(float4*)&Y[(size_t)m * DD + n0 + (tx << 2)] = r0;
        float2 p2 = unpack2(acc[mi][2]);
        float2 p3 = unpack2(acc[mi][3]);
        float4 r1 = { p2.x + bv1.x, p2.y + bv1.y, p3.x + bv1.z, p3.y + bv1.w };
        *(float4*)&Y[(size_t)m * DD + n0 + 64 + (tx << 2)] = r1;
    }
}

__global__ __launch_bounds__(256, 2) void gemm_qkv(
    const float* __restrict__ X,
    const float* __restrict__ Wq, const float* __restrict__ Wk, const float* __restrict__ Wv,
    const float* __restrict__ bq, const float* __restrict__ bk, const float* __restrict__ bv,
    float* __restrict__ Yq, float* __restrict__ Yk, float* __restrict__ Yv)
{
    const int z = blockIdx.z;
    const float* W = (z == 0) ? Wq : (z == 1) ? Wk : Wv;
    const float* b = (z == 0) ? bq : (z == 1) ? bk : bv;
    float*       Y = (z == 0) ? Yq : (z == 1) ? Yk : Yv;
    gemm_body(X, W, b, Y, blockIdx.x * 128, blockIdx.y * 128);
}

__global__ __launch_bounds__(256, 2) void gemm_single(
    const float* __restrict__ X, const float* __restrict__ W,
    const float* __restrict__ bias, float* __restrict__ Y)
{
    gemm_body(X, W, bias, Y, blockIdx.x * 128, blockIdx.y * 128);
}

// ---------------------------------------------------------------------------
// Banded sparse attention — GEMM-structured.  64 queries per block.
// Scores: S(64x32) over d=64, Qst[d][q] + Kst[d][k], thread = 2q x 4k.
// AV:     O(64x64) over k=32, Ps[k][q]  + Vs[k][d],  thread = 4q x 4d.
// Softmax state passed between mappings via Msm/sfsm/lsm smem arrays.
// ---------------------------------------------------------------------------
__global__ __launch_bounds__(256, 3) void attn_banded(
    const float* __restrict__ pos,
    const int* __restrict__ p_md, const int* __restrict__ p_tw)
{
    __shared__ float  Qst[64][68];   // Q^T: [d][q], pre-scaled
    __shared__ float  Kst[64][36];   // K^T chunk: [d][key]
    __shared__ float  Vs[32][68];    // V chunk: [key][d]
    __shared__ float  Ps[32][68];    // probs: [key][q]
    __shared__ float  Msm[64], sfsm[64], lsm[64];
    __shared__ float2 posm[32];      // key positions for chunk

    const int a    = blockIdx.z;
    const int h    = blockIdx.y;
    const int q0   = blockIdx.x * 64;
    const int tid  = threadIdx.x;
    const int lane = tid & 31;

    // scores mapping: 2q x 4k
    const int tx2 = lane >> 2;                        // 0..7  (keys tx2*4..+3)
    const int ty2 = ((tid >> 5) << 2) + (lane & 3);   // 0..31 (queries ty2*2..+1)
    // AV mapping: 4q x 4d
    const int tx3 = tid & 15;                         // d-quad
    const int ty3 = tid >> 4;                         // q-quad

    const int   tw  = *p_tw;
    const float mdf = (float)(*p_md);
    const float md2 = mdf * mdf;

    // ---- stage Q^T (prescaled by 1/sqrt(64)), init Msm ----
    {
        const int d  = tid >> 2;
        const int qq = (tid & 3) << 4;
        const float* qb = g_q + (size_t)(a*TT + q0) * DD + h*HDIM + d;
        #pragma unroll
        for (int j = 0; j < 4; j++) {
            float4 t;
            t.x = qb[(size_t)(qq + j*4 + 0) * DD] * 0.125f;
            t.y = qb[(size_t)(qq + j*4 + 1) * DD] * 0.125f;
            t.z = qb[(size_t)(qq + j*4 + 2) * DD] * 0.125f;
            t.w = qb[(size_t)(qq + j*4 + 3) * DD] * 0.125f;
            *(float4*)&Qst[d][qq + j*4] = t;
        }
    }
    if (tid < 64) Msm[tid] = -1e30f;

    // q positions for scores mapping
    float pqx[2], pqy[2];
    #pragma unroll
    for (int qi = 0; qi < 2; qi++) {
        const int qg = q0 + (ty2 << 1) + qi;
        pqx[qi] = pos[(size_t)(a*TT + qg)*2 + 0];
        pqy[qi] = pos[(size_t)(a*TT + qg)*2 + 1];
    }
    float lpart[2] = {0.f, 0.f};
    ull   o2[4][2];
    #pragma unroll
    for (int i = 0; i < 4; i++) { o2[i][0] = 0ull; o2[i][1] = 0ull; }

    int jlo = q0 - tw;       if (jlo < 0)      jlo = 0;
    int jhi = q0 + 63 + tw;  if (jhi > TT - 1) jhi = TT - 1;

    const float* kroot = g_k + (size_t)a*TT*DD + h*HDIM;
    const float* vroot = g_v + (size_t)a*TT*DD + h*HDIM;

    for (int c0 = jlo; c0 <= jhi; c0 += 32) {
        const int cn = min(32, jhi - c0 + 1);

        __syncthreads();   // prior chunk's scores (Kst) and AV (Vs/Ps) done
        // stage K^T: thread = (d, 8 keys)
        {
            const int d  = tid >> 2;
            const int kq = (tid & 3) << 3;
            const float* kb = kroot + (size_t)c0 * DD + d;
            float t[8];
            #pragma unroll
            for (int u = 0; u < 8; u++)
                t[u] = (kq + u < cn) ? kb[(size_t)(kq + u) * DD] : 0.f;
            float4 t0 = {t[0], t[1], t[2], t[3]};
            float4 t1 = {t[4], t[5], t[6], t[7]};
            *(float4*)&Kst[d][kq]     = t0;
            *(float4*)&Kst[d][kq + 4] = t1;
        }
        // stage V rows (zero tail)
        {
            const int r0 = tid >> 4;
            const int c4 = (tid & 15) << 2;
            #pragma unroll
            for (int u = 0; u < 2; u++) {
                const int r = r0 + u*16;
                float4 v = {0.f, 0.f, 0.f, 0.f};
                if (r < cn) v = *(const float4*)&vroot[(size_t)(c0 + r) * DD + c4];
                *(float4*)&Vs[r][c4] = v;
            }
        }
        if (tid < 32) {
            const int idx = min(c0 + tid, TT - 1);
            posm[tid] = *(const float2*)&pos[(size_t)(a*TT + idx)*2];
        }
        __syncthreads();

        // ---- scores micro-GEMM: acc[2q][2 key-pairs] ----
        ull acc[2][2] = {{0ull, 0ull}, {0ull, 0ull}};
        #pragma unroll
        for (int d = 0; d < 64; d++) {
            const float2     qa = *(const float2*)&Qst[d][ty2 << 1];
            const ulonglong2 kb = *(const ulonglong2*)&Kst[d][tx2 << 2];
            const ull a0 = dup2(qa.x), a1 = dup2(qa.y);
            fma2(acc[0][0], a0, kb.x); fma2(acc[0][1], a0, kb.y);
            fma2(acc[1][0], a1, kb.x); fma2(acc[1][1], a1, kb.y);
        }

        // ---- mask + online softmax ----
        const int kb0 = tx2 << 2;
        float2 pk[4];
        #pragma unroll
        for (int j = 0; j < 4; j++) pk[j] = posm[kb0 + j];

        float pmat[2][4];
        #pragma unroll
        for (int qi = 0; qi < 2; qi++) {
            const int qg = q0 + (ty2 << 1) + qi;
            float s[4];
            { float2 v0 = unpack2(acc[qi][0]); float2 v1 = unpack2(acc[qi][1]);
              s[0] = v0.x; s[1] = v0.y; s[2] = v1.x; s[3] = v1.y; }
            bool okk[4];
            #pragma unroll
            for (int j = 0; j < 4; j++) {
                const int jg = c0 + kb0 + j;
                int dt = qg - jg; dt = dt < 0 ? -dt : dt;
                const float dx = pqx[qi] - pk[j].x;
                const float dy = pqy[qi] - pk[j].y;
                okk[j] = (kb0 + j < cn) && (dt <= tw) && (dx*dx + dy*dy <= md2);
                if (!okk[j]) s[j] = -1e30f;
            }
            float cm = fmaxf(fmaxf(s[0], s[1]), fmaxf(s[2], s[3]));
            cm = fmaxf(cm, __shfl_xor_sync(0xffffffffu, cm, 4));
            cm = fmaxf(cm, __shfl_xor_sync(0xffffffffu, cm, 8));
            cm = fmaxf(cm, __shfl_xor_sync(0xffffffffu, cm, 16));

            const float mold = Msm[(ty2 << 1) + qi];
            const float mi   = fmaxf(mold, cm);
            const float sf   = __expf(mold - mi);
            float psum = 0.f;
            #pragma unroll
            for (int j = 0; j < 4; j++) {
                const float p = okk[j] ? __expf(s[j] - mi) : 0.f;
                pmat[qi][j] = p;
                psum += p;
            }
            lpart[qi] = lpart[qi] * sf + psum;
            if (tx2 == 0) {
                sfsm[(ty2 << 1) + qi] = sf;
                Msm [(ty2 << 1) + qi] = mi;
            }
        }
        // store probs: Ps[key][q]
        #pragma unroll
        for (int j = 0; j < 4; j++) {
            float2 pr = { pmat[0][j], pmat[1][j] };
            *(float2*)&Ps[kb0 + j][ty2 << 1] = pr;
        }
        __syncthreads();

        // ---- AV micro-GEMM: o(4q x 4d) over 32 keys ----
        {
            const float4 sfv = *(const float4*)&sfsm[ty3 << 2];
            o2[0][0] = mul2(o2[0][0], dup2(sfv.x)); o2[0][1] = mul2(o2[0][1], dup2(sfv.x));
            o2[1][0] = mul2(o2[1][0], dup2(sfv.y)); o2[1][1] = mul2(o2[1][1], dup2(sfv.y));
            o2[2][0] = mul2(o2[2][0], dup2(sfv.z)); o2[2][1] = mul2(o2[2][1], dup2(sfv.z));
            o2[3][0] = mul2(o2[3][0], dup2(sfv.w)); o2[3][1] = mul2(o2[3][1], dup2(sfv.w));
        }
        #pragma unroll
        for (int kk = 0; kk < 32; kk++) {
            const float4     pa = *(const float4*)&Ps[kk][ty3 << 2];
            const ulonglong2 vb = *(const ulonglong2*)&Vs[kk][tx3 << 2];
            const ull p0 = dup2(pa.x), p1 = dup2(pa.y), p2 = dup2(pa.z), p3 = dup2(pa.w);
            fma2(o2[0][0], p0, vb.x); fma2(o2[0][1], p0, vb.y);
            fma2(o2[1][0], p1, vb.x); fma2(o2[1][1], p1, vb.y);
            fma2(o2[2][0], p2, vb.x); fma2(o2[2][1], p2, vb.y);
            fma2(o2[3][0], p3, vb.x); fma2(o2[3][1], p3, vb.y);
        }
    }

    // ---- finalize: normalizer reduce, write context ----
    #pragma unroll
    for (int qi = 0; qi < 2; qi++) {
        float cs = lpart[qi];
        cs += __shfl_xor_sync(0xffffffffu, cs, 4);
        cs += __shfl_xor_sync(0xffffffffu, cs, 8);
        cs += __shfl_xor_sync(0xffffffffu, cs, 16);
        if (tx2 == 0) lsm[(ty2 << 1) + qi] = cs;
    }
    __syncthreads();
    {
        const float4 lv = *(const float4*)&lsm[ty3 << 2];
        const float inv[4] = { 1.f/lv.x, 1.f/lv.y, 1.f/lv.z, 1.f/lv.w };
        #pragma unroll
        for (int qi = 0; qi < 4; qi++) {
            const int qg = q0 + (ty3 << 2) + qi;
            float2 oa = unpack2(o2[qi][0]);
            float2 ob = unpack2(o2[qi][1]);
            float4 r = { oa.x*inv[qi], oa.y*inv[qi], ob.x*inv[qi], ob.y*inv[qi] };
            *(float4*)&g_ctx[(size_t)(a*TT + qg) * DD + h*HDIM + (tx3 << 2)] = r;
        }
    }
}

// ---------------------------------------------------------------------------
// Launch
// ---------------------------------------------------------------------------
extern "C" void kernel_launch(void* const* d_in, const int* in_sizes, int n_in,
                              void* d_out, int out_size)
{
    const float* feat = (const float*)d_in[0];
    const float* posn = (const float*)d_in[1];
    const float* Wq   = (const float*)d_in[2];
    const float* bq   = (const float*)d_in[3];
    const float* Wk   = (const float*)d_in[4];
    const float* bk   = (const float*)d_in[5];
    const float* Wv   = (const float*)d_in[6];
    const float* bv   = (const float*)d_in[7];
    const float* Wo   = (const float*)d_in[8];
    const float* bo   = (const float*)d_in[9];
    const int*   pmd  = (const int*)d_in[10];
    const int*   ptw  = (const int*)d_in[11];

    void *pq, *pk, *pv, *pctx;
    cudaGetSymbolAddress(&pq,   g_q);
    cudaGetSymbolAddress(&pk,   g_k);
    cudaGetSymbolAddress(&pv,   g_v);
    cudaGetSymbolAddress(&pctx, g_ctx);

    gemm_qkv<<<dim3(AT/128, DD/128, 3), 256>>>(
        feat, Wq, Wk, Wv, bq, bk, bv, (float*)pq, (float*)pk, (float*)pv);

    attn_banded<<<dim3(TT/64, HH, AA), 256>>>(posn, pmd, ptw);

    gemm_single<<<dim3(AT/128, DD/128, 1), 256>>>(
        (const float*)pctx, Wo, bo, (float*)d_out);
}

// round 17
// speedup vs baseline: 1.2179x; 1.0143x over previous
#include <cuda_runtime.h>

#define AA   64
#define TT   512
#define DD   256
#define HH   4
#define HDIM 64
#define AT   (AA*TT)

typedef unsigned long long ull;

// Scratch (allocation-free)
__device__ float g_q[AT*DD];
__device__ float g_k[AT*DD];
__device__ float g_v[AT*DD];
__device__ float g_ctx[AT*DD];

// ---------------------------------------------------------------------------
// f32x2 packed-math helpers (base-sm_103 FFMA2 path — ptxas never auto-emits)
// ---------------------------------------------------------------------------
__device__ __forceinline__ ull dup2(float x) {
    ull r;
    asm("mov.b64 %0, {%1, %1};" : "=l"(r) : "r"(__float_as_uint(x)));
    return r;
}
__device__ __forceinline__ ull pack2(float x, float y) {
    ull r;
    asm("mov.b64 %0, {%1, %2};" : "=l"(r) : "r"(__float_as_uint(x)), "r"(__float_as_uint(y)));
    return r;
}
__device__ __forceinline__ void fma2(ull &d, ull a, ull b) {
    asm("fma.rn.f32x2 %0, %1, %2, %0;" : "+l"(d) : "l"(a), "l"(b));
}
__device__ __forceinline__ ull mul2(ull a, ull b) {
    ull r;
    asm("mul.rn.f32x2 %0, %1, %2;" : "=l"(r) : "l"(a), "l"(b));
    return r;
}
__device__ __forceinline__ float2 unpack2(ull v) {
    float2 f;
    asm("mov.b64 {%0, %1}, %2;" : "=f"(f.x), "=f"(f.y) : "l"(v));
    return f;
}

// ---------------------------------------------------------------------------
// GEMM (exact R8): BM=BN=128, BK=16, double-buffered, FFMA2.
// ---------------------------------------------------------------------------
__device__ __forceinline__ void gemm_tile(
    const float (* __restrict__ Ak)[132], const float (* __restrict__ Bk)[132],
    int tx, int ty, ull acc[8][4])
{
    #pragma unroll
    for (int k = 0; k < 16; k++) {
        const float4     a0 = *(const float4*)&Ak[k][ty << 2];
        const float4     a1 = *(const float4*)&Ak[k][64 + (ty << 2)];
        const ulonglong2 b0 = *(const ulonglong2*)&Bk[k][tx << 2];
        const ulonglong2 b1 = *(const ulonglong2*)&Bk[k][64 + (tx << 2)];
        ull am[8] = { dup2(a0.x), dup2(a0.y), dup2(a0.z), dup2(a0.w),
                      dup2(a1.x), dup2(a1.y), dup2(a1.z), dup2(a1.w) };
        #pragma unroll
        for (int mi = 0; mi < 8; mi++) {
            fma2(acc[mi][0], am[mi], b0.x);
            fma2(acc[mi][1], am[mi], b0.y);
            fma2(acc[mi][2], am[mi], b1.x);
            fma2(acc[mi][3], am[mi], b1.y);
        }
    }
}

__device__ __forceinline__ void gemm_body(
    const float* __restrict__ X, const float* __restrict__ W,
    const float* __restrict__ bias, float* __restrict__ Y,
    int m0, int n0)
{
    __shared__ float As[2][16][132];
    __shared__ float Bs[2][16][132];

    const int tid = threadIdx.x;
    const int tx  = tid & 15;
    const int ty  = tid >> 4;
    const int lr  = tid >> 2;
    const int lc  = (tid & 3) << 2;

    ull acc[8][4];
    #pragma unroll
    for (int i = 0; i < 8; i++)
        #pragma unroll
        for (int j = 0; j < 4; j++) acc[i][j] = 0ull;

    const float* xp0 = &X[(size_t)(m0 + lr)      * DD + lc];
    const float* xp1 = &X[(size_t)(m0 + 64 + lr) * DD + lc];
    const float* wp0 = &W[(size_t)(n0 + lr)      * DD + lc];
    const float* wp1 = &W[(size_t)(n0 + 64 + lr) * DD + lc];

    {
        float4 x0 = *(const float4*)(xp0);
        float4 x1 = *(const float4*)(xp1);
        float4 w0 = *(const float4*)(wp0);
        float4 w1 = *(const float4*)(wp1);
        As[0][lc+0][lr] = x0.x; As[0][lc+1][lr] = x0.y; As[0][lc+2][lr] = x0.z; As[0][lc+3][lr] = x0.w;
        As[0][lc+0][64+lr] = x1.x; As[0][lc+1][64+lr] = x1.y; As[0][lc+2][64+lr] = x1.z; As[0][lc+3][64+lr] = x1.w;
        Bs[0][lc+0][lr] = w0.x; Bs[0][lc+1][lr] = w0.y; Bs[0][lc+2][lr] = w0.z; Bs[0][lc+3][lr] = w0.w;
        Bs[0][lc+0][64+lr] = w1.x; Bs[0][lc+1][64+lr] = w1.y; Bs[0][lc+2][64+lr] = w1.z; Bs[0][lc+3][64+lr] = w1.w;
    }
    __syncthreads();

    int p = 0;
    for (int k0 = 16; k0 < 256; k0 += 16) {
        float4 x0 = *(const float4*)(xp0 + k0);
        float4 x1 = *(const float4*)(xp1 + k0);
        float4 w0 = *(const float4*)(wp0 + k0);
        float4 w1 = *(const float4*)(wp1 + k0);

        gemm_tile(As[p], Bs[p], tx, ty, acc);

        const int q = p ^ 1;
        As[q][lc+0][lr] = x0.x; As[q][lc+1][lr] = x0.y; As[q][lc+2][lr] = x0.z; As[q][lc+3][lr] = x0.w;
        As[q][lc+0][64+lr] = x1.x; As[q][lc+1][64+lr] = x1.y; As[q][lc+2][64+lr] = x1.z; As[q][lc+3][64+lr] = x1.w;
        Bs[q][lc+0][lr] = w0.x; Bs[q][lc+1][lr] = w0.y; Bs[q][lc+2][lr] = w0.z; Bs[q][lc+3][lr] = w0.w;
        Bs[q][lc+0][64+lr] = w1.x; Bs[q][lc+1][64+lr] = w1.y; Bs[q][lc+2][64+lr] = w1.z; Bs[q][lc+3][64+lr] = w1.w;
        __syncthreads();
        p = q;
    }
    gemm_tile(As[p], Bs[p], tx, ty, acc);

    float4 bv0 = *(const float4*)&bias[n0 + (tx << 2)];
    float4 bv1 = *(const float4*)&bias[n0 + 64 + (tx << 2)];
    #pragma unroll
    for (int mi = 0; mi < 8; mi++) {
        const int m = m0 + ((mi < 4) ? ((ty << 2) + mi) : (64 + (ty << 2) + mi - 4));
        float2 p0 = unpack2(acc[mi][0]);
        float2 p1 = unpack2(acc[mi][1]);
        float4 r0 = { p0.x + bv0.x, p0.y + bv0.y, p1.x + bv0.z, p1.y + bv0.w };
        *(float4*)&Y[(size_t)m * DD + n0 + (tx << 2)] = r0;
        float2 p2 = unpack2(acc[mi][2]);
        float2 p3 = unpack2(acc[mi][3]);
        float4 r1 = { p2.x + bv1.x, p2.y + bv1.y, p3.x + bv1.z, p3.y + bv1.w };
        *(float4*)&Y[(size_t)m * DD + n0 + 64 + (tx << 2)] = r1;
    }
}

__global__ __launch_bounds__(256, 2) void gemm_qkv(
    const float* __restrict__ X,
    const float* __restrict__ Wq, const float* __restrict__ Wk, const float* __restrict__ Wv,
    const float* __restrict__ bq, const float* __restrict__ bk, const float* __restrict__ bv,
    float* __restrict__ Yq, float* __restrict__ Yk, float* __restrict__ Yv)
{
    const int z = blockIdx.z;
    const float* W = (z == 0) ? Wq : (z == 1) ? Wk : Wv;
    const float* b = (z == 0) ? bq : (z == 1) ? bk : bv;
    float*       Y = (z == 0) ? Yq : (z == 1) ? Yk : Yv;
    gemm_body(X, W, b, Y, blockIdx.x * 128, blockIdx.y * 128);
}

__global__ __launch_bounds__(256, 2) void gemm_single(
    const float* __restrict__ X, const float* __restrict__ W,
    const float* __restrict__ bias, float* __restrict__ Y)
{
    gemm_body(X, W, bias, Y, blockIdx.x * 128, blockIdx.y * 128);
}

// ---------------------------------------------------------------------------
// Banded sparse attention — GEMM-structured (R16) with d-PACKED scores:
// Qp[d2][q], Kp[d2][key] hold f32x2 (d, d+1) pairs; the scores micro-GEMM
// runs 32 packed d-steps with NO dup MOVs and 25% fewer LDS wavefronts.
// AV identical to R16 (Ps[k][q] float + Vs[k][d]).
// ---------------------------------------------------------------------------
__global__ __launch_bounds__(256, 3) void attn_banded(
    const float* __restrict__ pos,
    const int* __restrict__ p_md, const int* __restrict__ p_tw)
{
    __shared__ ull    Qp[32][66];    // [d2][q] packed (even stride: 16B-aligned rows)
    __shared__ ull    Kp[32][34];    // [d2][key] packed
    __shared__ float  Vs[32][68];    // V chunk: [key][d]
    __shared__ float  Ps[32][68];    // probs: [key][q]
    __shared__ float  Msm[64], sfsm[64], lsm[64];
    __shared__ float2 posm[32];      // key positions for chunk

    const int a    = blockIdx.z;
    const int h    = blockIdx.y;
    const int q0   = blockIdx.x * 64;
    const int tid  = threadIdx.x;
    const int lane = tid & 31;

    // scores mapping: 2q x 4k
    const int tx2 = lane >> 2;                        // 0..7  (keys tx2*4..+3)
    const int ty2 = ((tid >> 5) << 2) + (lane & 3);   // 0..31 (queries ty2*2..+1)
    // AV mapping: 4q x 4d
    const int tx3 = tid & 15;                         // d-quad
    const int ty3 = tid >> 4;                         // q-quad

    const int   tw  = *p_tw;
    const float mdf = (float)(*p_md);
    const float md2 = mdf * mdf;

    // ---- stage Qp (d-pair packed, prescaled by 1/8), init Msm ----
    {
        // thread: d2 = lane, queries (tid>>5)*8 .. +7  (coalesced LDG.64 per q)
        const float* qb = g_q + (size_t)(a*TT + q0) * DD + h*HDIM + (lane << 1);
        const int qq = (tid >> 5) << 3;
        #pragma unroll
        for (int j = 0; j < 8; j++) {
            float2 t = *(const float2*)&qb[(size_t)(qq + j) * DD];
            Qp[lane][qq + j] = pack2(t.x * 0.125f, t.y * 0.125f);
        }
    }
    if (tid < 64) Msm[tid] = -1e30f;

    // q positions for scores mapping
    float pqx[2], pqy[2];
    #pragma unroll
    for (int qi = 0; qi < 2; qi++) {
        const int qg = q0 + (ty2 << 1) + qi;
        pqx[qi] = pos[(size_t)(a*TT + qg)*2 + 0];
        pqy[qi] = pos[(size_t)(a*TT + qg)*2 + 1];
    }
    float lpart[2] = {0.f, 0.f};
    ull   o2[4][2];
    #pragma unroll
    for (int i = 0; i < 4; i++) { o2[i][0] = 0ull; o2[i][1] = 0ull; }

    int jlo = q0 - tw;       if (jlo < 0)      jlo = 0;
    int jhi = q0 + 63 + tw;  if (jhi > TT - 1) jhi = TT - 1;

    const float* kroot = g_k + (size_t)a*TT*DD + h*HDIM;
    const float* vroot = g_v + (size_t)a*TT*DD + h*HDIM;

    for (int c0 = jlo; c0 <= jhi; c0 += 32) {
        const int cn = min(32, jhi - c0 + 1);

        __syncthreads();   // prior chunk's reads of Kp/Vs/Ps done
        // stage Kp: thread = d2 (lane), 4 keys (coalesced LDG.64 per key)
        {
            const float* kb = kroot + (size_t)c0 * DD + (lane << 1);
            const int kq = (tid >> 5) << 2;
            #pragma unroll
            for (int u = 0; u < 4; u++) {
                const int k = kq + u;
                float2 t = {0.f, 0.f};
                if (k < cn) t = *(const float2*)&kb[(size_t)k * DD];
                Kp[lane][k] = pack2(t.x, t.y);
            }
        }
        // stage V rows (zero tail)
        {
            const int r0 = tid >> 4;
            const int c4 = (tid & 15) << 2;
            #pragma unroll
            for (int u = 0; u < 2; u++) {
                const int r = r0 + u*16;
                float4 v = {0.f, 0.f, 0.f, 0.f};
                if (r < cn) v = *(const float4*)&vroot[(size_t)(c0 + r) * DD + c4];
                *(float4*)&Vs[r][c4] = v;
            }
        }
        if (tid < 32) {
            const int idx = min(c0 + tid, TT - 1);
            posm[tid] = *(const float2*)&pos[(size_t)(a*TT + idx)*2];
        }
        __syncthreads();

        // ---- scores micro-GEMM, d-packed: acc[2q][4k] (packed over d-parity) ----
        ull acc[2][4];
        #pragma unroll
        for (int i = 0; i < 2; i++)
            #pragma unroll
            for (int j = 0; j < 4; j++) acc[i][j] = 0ull;

        #pragma unroll
        for (int d2 = 0; d2 < 32; d2++) {
            const ulonglong2 qa = *(const ulonglong2*)&Qp[d2][ty2 << 1];
            const ulonglong2 k0 = *(const ulonglong2*)&Kp[d2][tx2 << 2];
            const ulonglong2 k1 = *(const ulonglong2*)&Kp[d2][(tx2 << 2) + 2];
            fma2(acc[0][0], qa.x, k0.x); fma2(acc[0][1], qa.x, k0.y);
            fma2(acc[0][2], qa.x, k1.x); fma2(acc[0][3], qa.x, k1.y);
            fma2(acc[1][0], qa.y, k0.x); fma2(acc[1][1], qa.y, k0.y);
            fma2(acc[1][2], qa.y, k1.x); fma2(acc[1][3], qa.y, k1.y);
        }

        // ---- mask + online softmax ----
        const int kb0 = tx2 << 2;
        float2 pk[4];
        #pragma unroll
        for (int j = 0; j < 4; j++) pk[j] = posm[kb0 + j];

        float pmat[2][4];
        #pragma unroll
        for (int qi = 0; qi < 2; qi++) {
            const int qg = q0 + (ty2 << 1) + qi;
            float s[4];
            #pragma unroll
            for (int j = 0; j < 4; j++) {
                const float2 sv = unpack2(acc[qi][j]);
                s[j] = sv.x + sv.y;   // horizontal add over d-parity
            }
            bool okk[4];
            #pragma unroll
            for (int j = 0; j < 4; j++) {
                const int jg = c0 + kb0 + j;
                int dt = qg - jg; dt = dt < 0 ? -dt : dt;
                const float dx = pqx[qi] - pk[j].x;
                const float dy = pqy[qi] - pk[j].y;
                okk[j] = (kb0 + j < cn) && (dt <= tw) && (dx*dx + dy*dy <= md2);
                if (!okk[j]) s[j] = -1e30f;
            }
            float cm = fmaxf(fmaxf(s[0], s[1]), fmaxf(s[2], s[3]));
            cm = fmaxf(cm, __shfl_xor_sync(0xffffffffu, cm, 4));
            cm = fmaxf(cm, __shfl_xor_sync(0xffffffffu, cm, 8));
            cm = fmaxf(cm, __shfl_xor_sync(0xffffffffu, cm, 16));

            const float mold = Msm[(ty2 << 1) + qi];
            const float mi   = fmaxf(mold, cm);
            const float sf   = __expf(mold - mi);
            float psum = 0.f;
            #pragma unroll
            for (int j = 0; j < 4; j++) {
                const float p = okk[j] ? __expf(s[j] - mi) : 0.f;
                pmat[qi][j] = p;
                psum += p;
            }
            lpart[qi] = lpart[qi] * sf + psum;
            if (tx2 == 0) {
                sfsm[(ty2 << 1) + qi] = sf;
                Msm [(ty2 << 1) + qi] = mi;
            }
        }
        // store probs: Ps[key][q]
        #pragma unroll
        for (int j = 0; j < 4; j++) {
            float2 pr = { pmat[0][j], pmat[1][j] };
            *(float2*)&Ps[kb0 + j][ty2 << 1] = pr;
        }
        __syncthreads();

        // ---- AV micro-GEMM: o(4q x 4d) over 32 keys ----
        {
            const float4 sfv = *(const float4*)&sfsm[ty3 << 2];
            o2[0][0] = mul2(o2[0][0], dup2(sfv.x)); o2[0][1] = mul2(o2[0][1], dup2(sfv.x));
            o2[1][0] = mul2(o2[1][0], dup2(sfv.y)); o2[1][1] = mul2(o2[1][1], dup2(sfv.y));
            o2[2][0] = mul2(o2[2][0], dup2(sfv.z)); o2[2][1] = mul2(o2[2][1], dup2(sfv.z));
            o2[3][0] = mul2(o2[3][0], dup2(sfv.w)); o2[3][1] = mul2(o2[3][1], dup2(sfv.w));
        }
        #pragma unroll
        for (int kk = 0; kk < 32; kk++) {
            const float4     pa = *(const float4*)&Ps[kk][ty3 << 2];
            const ulonglong2 vb = *(const ulonglong2*)&Vs[kk][tx3 << 2];
            const ull p0 = dup2(pa.x), p1 = dup2(pa.y), p2 = dup2(pa.z), p3 = dup2(pa.w);
            fma2(o2[0][0], p0, vb.x); fma2(o2[0][1], p0, vb.y);
            fma2(o2[1][0], p1, vb.x); fma2(o2[1][1], p1, vb.y);
            fma2(o2[2][0], p2, vb.x); fma2(o2[2][1], p2, vb.y);
            fma2(o2[3][0], p3, vb.x); fma2(o2[3][1], p3, vb.y);
        }
    }

    // ---- finalize: normalizer reduce, write context ----
    #pragma unroll
    for (int qi = 0; qi < 2; qi++) {
        float cs = lpart[qi];
        cs += __shfl_xor_sync(0xffffffffu, cs, 4);
        cs += __shfl_xor_sync(0xffffffffu, cs, 8);
        cs += __shfl_xor_sync(0xffffffffu, cs, 16);
        if (tx2 == 0) lsm[(ty2 << 1) + qi] = cs;
    }
    __syncthreads();
    {
        const float4 lv = *(const float4*)&lsm[ty3 << 2];
        const float inv[4] = { 1.f/lv.x, 1.f/lv.y, 1.f/lv.z, 1.f/lv.w };
        #pragma unroll
        for (int qi = 0; qi < 4; qi++) {
            const int qg = q0 + (ty3 << 2) + qi;
            float2 oa = unpack2(o2[qi][0]);
            float2 ob = unpack2(o2[qi][1]);
            float4 r = { oa.x*inv[qi], oa.y*inv[qi], ob.x*inv[qi], ob.y*inv[qi] };
            *(float4*)&g_ctx[(size_t)(a*TT + qg) * DD + h*HDIM + (tx3 << 2)] = r;
        }
    }
}

// ---------------------------------------------------------------------------
// Launch
// ---------------------------------------------------------------------------
extern "C" void kernel_launch(void* const* d_in, const int* in_sizes, int n_in,
                              void* d_out, int out_size)
{
    const float* feat = (const float*)d_in[0];
    const float* posn = (const float*)d_in[1];
    const float* Wq   = (const float*)d_in[2];
    const float* bq   = (const float*)d_in[3];
    const float* Wk   = (const float*)d_in[4];
    const float* bk   = (const float*)d_in[5];
    const float* Wv   = (const float*)d_in[6];
    const float* bv   = (const float*)d_in[7];
    const float* Wo   = (const float*)d_in[8];
    const float* bo   = (const float*)d_in[9];
    const int*   pmd  = (const int*)d_in[10];
    const int*   ptw  = (const int*)d_in[11];

    void *pq, *pk, *pv, *pctx;
    cudaGetSymbolAddress(&pq,   g_q);
    cudaGetSymbolAddress(&pk,   g_k);
    cudaGetSymbolAddress(&pv,   g_v);
    cudaGetSymbolAddress(&pctx, g_ctx);

    gemm_qkv<<<dim3(AT/128, DD/128, 3), 256>>>(
        feat, Wq, Wk, Wv, bq, bk, bv, (float*)pq, (float*)pk, (float*)pv);

    attn_banded<<<dim3(TT/64, HH, AA), 256>>>(posn, pmd, ptw);

    gemm_single<<<dim3(AT/128, DD/128, 1), 256>>>(
        (const float*)pctx, Wo, bo, (float*)d_out);
}